// round 2
// baseline (speedup 1.0000x reference)
#include <cuda_runtime.h>
#include <stdint.h>

#define B_   8
#define C_   64
#define NV   40962
#define K_   7
#define CK   448           // C_ * K_
#define VT   256           // vertices per main-kernel block
#define GSTRIDE 65         // padded G row (gcd(65,32)=1 -> conflict-free)

// Scratch (static device globals; no runtime allocation allowed)
__device__ float g_xt[(size_t)B_ * NV * C_];   // x transposed: [b][n][c], 84 MB
__device__ float g_wt[CK * C_];                // W permuted:  [k][c][o], 112 KB

// ---------------------------------------------------------------------------
// Kernel 1: transpose x [B,C,N] -> xt [B,N,C] so gathers become contiguous 256B rows
// ---------------------------------------------------------------------------
__global__ void xt_transpose_kernel(const float* __restrict__ x) {
    __shared__ float tile[32][33];
    const int b  = blockIdx.z;
    const int c0 = blockIdx.y * 32;
    const int n0 = blockIdx.x * 32;
    const int tx = threadIdx.x;   // 0..31
    const int ty = threadIdx.y;   // 0..7

    #pragma unroll
    for (int s = 0; s < 4; s++) {
        const int c = c0 + ty + s * 8;       // always < 64
        const int n = n0 + tx;
        float v = 0.0f;
        if (n < NV) v = x[((size_t)b * C_ + c) * NV + n];
        tile[ty + s * 8][tx] = v;
    }
    __syncthreads();
    #pragma unroll
    for (int s = 0; s < 4; s++) {
        const int n = n0 + ty + s * 8;
        const int c = c0 + tx;
        if (n < NV)
            g_xt[((size_t)b * NV + n) * C_ + c] = tile[tx][ty + s * 8];
    }
}

// ---------------------------------------------------------------------------
// Kernel 2: permute W [o][c*7+k] -> Wt [(k*64+c)*64 + o]
// ---------------------------------------------------------------------------
__global__ void wprep_kernel(const float* __restrict__ W) {
    const int e = blockIdx.x * 256 + threadIdx.x;
    if (e >= CK * C_) return;
    const int o = e & 63;
    const int c = (e >> 6) & 63;
    const int k = e >> 12;
    g_wt[e] = W[o * CK + c * K_ + k];
}

// ---------------------------------------------------------------------------
// Kernel 3: main gather + GEMM.
// Block: 256 threads, handles (batch b, 256 vertices).
// smem: full Wt (112 KB) + gathered tile G[256][GSTRIDE] per k (65 KB).
// Thread (to = warpid, tv = lane): 8 vertices (v = i*32+tv) x 8 outputs (o = to*8+j).
// ---------------------------------------------------------------------------
extern __shared__ float smem[];

__global__ __launch_bounds__(256, 1)
void iconv_main_kernel(const int* __restrict__ neigh,
                       const float* __restrict__ bias,
                       float* __restrict__ out) {
    float* sW = smem;                     // CK*64 = 28672 floats
    float* sG = smem + CK * C_;           // VT*GSTRIDE = 16640 floats

    const int b    = blockIdx.y;
    const int n0   = blockIdx.x * VT;
    const int vmax = min(VT, NV - n0);
    const int tid  = threadIdx.x;

    // Stage Wt into smem with coalesced float4 copies (Wt is L2-resident)
    {
        const float4* src = (const float4*)g_wt;
        float4*       dst = (float4*)sW;
        #pragma unroll 4
        for (int i = tid; i < (CK * C_) / 4; i += 256) dst[i] = src[i];
    }

    const int tv = tid & 31;     // lane   -> vertex interleave
    const int to = tid >> 5;     // warpid -> output group (o = to*8 + j)

    float bias_r[8];
    #pragma unroll
    for (int j = 0; j < 8; j++) bias_r[j] = bias[to * 8 + j];

    float acc[8][8];
    #pragma unroll
    for (int i = 0; i < 8; i++)
        #pragma unroll
        for (int j = 0; j < 8; j++) acc[i][j] = 0.0f;

    const float* xtb = g_xt + (size_t)b * NV * C_;

    // gather thread mapping: 4 threads per vertex, 64 vertices per pass
    const int q    = tid & 3;    // 16-float chunk within the 64-float row
    const int vloc = tid >> 2;   // 0..63

    for (int k = 0; k < K_; k++) {
        __syncthreads();   // previous compute done before overwriting sG

        // ---- gather 256 vertex rows (256B each, coalesced in 64B quarters)
        #pragma unroll
        for (int p = 0; p < 4; p++) {
            const int v = p * 64 + vloc;
            if (v < vmax) {
                const int j = neigh[(size_t)(n0 + v) * K_ + k];
                const float4* row = (const float4*)(xtb + (size_t)j * C_);
                float* dstrow = sG + v * GSTRIDE;
                #pragma unroll
                for (int t = 0; t < 4; t++) {
                    const float4 val = row[q * 4 + t];
                    const int cb = q * 16 + t * 4;
                    dstrow[cb + 0] = val.x; dstrow[cb + 1] = val.y;
                    dstrow[cb + 2] = val.z; dstrow[cb + 3] = val.w;
                }
            }
        }
        __syncthreads();

        // ---- accumulate 64 c-steps for this k
        const float* wk = sW + k * 64 * 64;
        #pragma unroll 4
        for (int c = 0; c < 64; c++) {
            // W: broadcast across the warp (all lanes same to) — 2x LDS.128
            const float4* wrow = (const float4*)(wk + c * 64 + to * 8);
            const float4 w0 = wrow[0];
            const float4 w1 = wrow[1];
            float w[8] = {w0.x, w0.y, w0.z, w0.w, w1.x, w1.y, w1.z, w1.w};

            // G: 8 conflict-free scalar LDS (bank = tv*65 mod 32 is a bijection)
            float g[8];
            #pragma unroll
            for (int i = 0; i < 8; i++)
                g[i] = sG[(i * 32 + tv) * GSTRIDE + c];

            #pragma unroll
            for (int i = 0; i < 8; i++)
                #pragma unroll
                for (int j = 0; j < 8; j++)
                    acc[i][j] = fmaf(g[i], w[j], acc[i][j]);
        }
    }

    // ---- store: coalesced 128B per (i,j) across lanes
    #pragma unroll
    for (int j = 0; j < 8; j++) {
        const int o = to * 8 + j;
        float* outp = out + ((size_t)b * C_ + o) * NV + n0;
        const float bj = bias_r[j];
        #pragma unroll
        for (int i = 0; i < 8; i++) {
            const int v = i * 32 + tv;
            if (v < vmax) outp[v] = acc[i][j] + bj;
        }
    }
}

// ---------------------------------------------------------------------------
// Launch
// ---------------------------------------------------------------------------
static const int SMEM_BYTES = (CK * C_ + VT * GSTRIDE) * (int)sizeof(float); // 181,248 B

extern "C" void kernel_launch(void* const* d_in, const int* in_sizes, int n_in,
                              void* d_out, int out_size) {
    const float* x     = (const float*)d_in[0];
    const int*   neigh = (const int*)d_in[1];    // JAX default x64-disabled: int32
    const float* W     = (const float*)d_in[2];
    const float* bias  = (const float*)d_in[3];
    float*       out   = (float*)d_out;

    // attribute set is immediate + idempotent (not a stream op, not an alloc)
    cudaFuncSetAttribute(iconv_main_kernel,
                         cudaFuncAttributeMaxDynamicSharedMemorySize, SMEM_BYTES);

    dim3 tgrid((NV + 31) / 32, C_ / 32, B_);     // (1281, 2, 8)
    xt_transpose_kernel<<<tgrid, dim3(32, 8)>>>(x);

    wprep_kernel<<<(CK * C_ + 255) / 256, 256>>>(W);

    dim3 mgrid((NV + VT - 1) / VT, B_);          // (161, 8)
    iconv_main_kernel<<<mgrid, 256, SMEM_BYTES>>>(neigh, bias, out);
}

// round 4
// speedup vs baseline: 1.8780x; 1.8780x over previous
#include <cuda_runtime.h>
#include <cuda_bf16.h>
#include <stdint.h>

#define B_   8
#define C_   64
#define NV   40962
#define K_   7
#define CK   448
#define VT   256            // vertices per main CTA

// ---------------------------------------------------------------------------
// Static device scratch (no runtime allocation allowed)
// ---------------------------------------------------------------------------
__device__ __align__(256) __nv_bfloat16 g_xhi[(size_t)B_ * NV * C_];  // [b][n][c] hi
__device__ __align__(256) __nv_bfloat16 g_xlo[(size_t)B_ * NV * C_];  // [b][n][c] lo
__device__ __align__(256) unsigned char g_wsw[K_ * 16384];            // [k][hi 8KB | lo 8KB], SW128

// ---------------------------------------------------------------------------
// PTX helpers (all baseline-sm_100-legal: cp.async, ldmatrix, mma.sync)
// ---------------------------------------------------------------------------
__device__ __forceinline__ uint32_t smem_u32(const void* p) {
    uint32_t a;
    asm("{ .reg .u64 t; cvta.to.shared.u64 t, %1; cvt.u32.u64 %0, t; }" : "=r"(a) : "l"(p));
    return a;
}
#define CP16(dst, src) \
    asm volatile("cp.async.cg.shared.global [%0], [%1], 16;" :: "r"(dst), "l"(src) : "memory")
#define CP_COMMIT() asm volatile("cp.async.commit_group;" ::: "memory")
#define CP_WAIT1()  asm volatile("cp.async.wait_group 1;" ::: "memory")
#define CP_WAIT0()  asm volatile("cp.async.wait_group 0;" ::: "memory")

#define LDM_X4(r0, r1, r2, r3, a) \
    asm volatile("ldmatrix.sync.aligned.m8n8.x4.shared.b16 {%0,%1,%2,%3}, [%4];" \
                 : "=r"(r0), "=r"(r1), "=r"(r2), "=r"(r3) : "r"(a))

#define MMA16816(d, a, b) \
    asm volatile("mma.sync.aligned.m16n8k16.row.col.f32.bf16.bf16.f32 " \
                 "{%0,%1,%2,%3}, {%4,%5,%6,%7}, {%8,%9}, {%0,%1,%2,%3};" \
                 : "+f"((d)[0]), "+f"((d)[1]), "+f"((d)[2]), "+f"((d)[3]) \
                 : "r"((a)[0]), "r"((a)[1]), "r"((a)[2]), "r"((a)[3]), \
                   "r"((b)[0]), "r"((b)[1]))

#define SWZ(o) ((o) ^ (((o) >> 3) & 0x70))

// ---------------------------------------------------------------------------
// SMEM layout (bytes)
// ---------------------------------------------------------------------------
#define SOFF_AHI(p)  ((p) * 81920)
#define SOFF_ALO(p)  ((p) * 81920 + 32768)
#define SOFF_W(p)    ((p) * 81920 + 65536)   // hi 8KB then lo 8KB
#define SOFF_NEIGH   163840                  // VT*K_*4 = 7168
#define SOFF_BIAS    171008                  // 256
#define SMEM_TOTAL   171264

// ---------------------------------------------------------------------------
// Kernel 1: split-transpose x [B,C,N] -> xt_hi/xt_lo [B,N,C] bf16
// ---------------------------------------------------------------------------
__global__ void xsplit_kernel(const float* __restrict__ x) {
    __shared__ float tile[32][33];
    const int b  = blockIdx.z;
    const int c0 = blockIdx.y * 32;
    const int n0 = blockIdx.x * 32;
    const int tx = threadIdx.x, ty = threadIdx.y;

    #pragma unroll
    for (int s = 0; s < 4; s++) {
        const int c = c0 + ty + s * 8;
        const int n = n0 + tx;
        float v = 0.0f;
        if (n < NV) v = x[((size_t)b * C_ + c) * NV + n];
        tile[ty + s * 8][tx] = v;
    }
    __syncthreads();
    #pragma unroll
    for (int s = 0; s < 4; s++) {
        const int n = n0 + ty + s * 8;
        const int c = c0 + tx;
        if (n < NV) {
            const float v = tile[tx][ty + s * 8];
            const __nv_bfloat16 h = __float2bfloat16(v);
            const __nv_bfloat16 l = __float2bfloat16(v - __bfloat162float(h));
            const size_t o = ((size_t)b * NV + n) * C_ + c;
            g_xhi[o] = h;
            g_xlo[o] = l;
        }
    }
}

// ---------------------------------------------------------------------------
// Kernel 2: W [o][c*7+k] -> SW128-swizzled bf16 tiles [k][hi/lo][o rows 128B]
// ---------------------------------------------------------------------------
__global__ void wprep_kernel(const float* __restrict__ W) {
    const int e = blockIdx.x * 256 + threadIdx.x;   // over 7*64*64
    if (e >= K_ * C_ * C_) return;
    const int c = e & 63;
    const int o = (e >> 6) & 63;
    const int k = e >> 12;
    const float v = W[o * CK + c * K_ + k];
    const __nv_bfloat16 h = __float2bfloat16(v);
    const __nv_bfloat16 l = __float2bfloat16(v - __bfloat162float(h));
    const uint32_t sw = SWZ((uint32_t)(o * 128 + c * 2));
    *(__nv_bfloat16*)(g_wsw + (size_t)k * 16384 + sw)        = h;
    *(__nv_bfloat16*)(g_wsw + (size_t)k * 16384 + 8192 + sw) = l;
}

// ---------------------------------------------------------------------------
// Kernel 3: gather + mma.sync main kernel. 1 CTA = (batch, 256 vertices).
// ---------------------------------------------------------------------------
extern __shared__ char smem_raw[];

__device__ __forceinline__ void stage_load(
    int p, int k, int vmax, const int* sN,
    const __nv_bfloat16* xhb, const __nv_bfloat16* xlb,
    uint32_t sb, int tid)
{
    const int v = tid;
    const int j = (v < vmax) ? sN[v * K_ + k] : 0;
    const char* srcH = (const char*)(xhb + (size_t)j * C_);
    const char* srcL = (const char*)(xlb + (size_t)j * C_);
    const uint32_t aH = sb + SOFF_AHI(p);
    const uint32_t aL = sb + SOFF_ALO(p);
    #pragma unroll
    for (int t = 0; t < 8; t++) {
        const uint32_t sw = SWZ((uint32_t)(v * 128 + t * 16));
        CP16(aH + sw, srcH + t * 16);
        CP16(aL + sw, srcL + t * 16);
    }
    const char* wsrc = (const char*)g_wsw + (size_t)k * 16384;   // pre-swizzled
    const uint32_t wdst = sb + SOFF_W(p);
    #pragma unroll
    for (int i = 0; i < 4; i++) {
        const int idx = tid + i * 256;
        CP16(wdst + (uint32_t)idx * 16, wsrc + (size_t)idx * 16);
    }
}

__global__ __launch_bounds__(256, 1)
void iconv_mma_kernel(const int* __restrict__ neigh,
                      const float* __restrict__ bias,
                      float* __restrict__ out) {
    const uint32_t sb = smem_u32(smem_raw);
    const int tid  = threadIdx.x;
    const int lane = tid & 31;
    const int b    = blockIdx.y;
    const int n0   = blockIdx.x * VT;
    const int vmax = min(VT, NV - n0);

    // stage bias + neighbor indices
    if (tid < C_) ((float*)(smem_raw + SOFF_BIAS))[tid] = bias[tid];
    {
        int* sN = (int*)(smem_raw + SOFF_NEIGH);
        const int lim = vmax * K_;
        #pragma unroll
        for (int i = 0; i < K_; i++) {
            const int q = tid + i * 256;
            if (q < VT * K_) sN[q] = (q < lim) ? neigh[(size_t)n0 * K_ + q] : 0;
        }
    }
    __syncthreads();

    const int* sN = (const int*)(smem_raw + SOFF_NEIGH);
    const __nv_bfloat16* xhb = g_xhi + (size_t)b * NV * C_;
    const __nv_bfloat16* xlb = g_xlo + (size_t)b * NV * C_;

    // per-lane ldmatrix address components
    const int mv = (tid >> 5) * 32;                       // warp's vertex base
    const int rowA = mv + (lane & 15);                    // + i*16
    const uint32_t halfA = (uint32_t)((lane >> 4) * 16);  // byte within k-chunk
    const int rowB = (lane & 7) + ((lane >> 4) << 3);     // + jp*16
    const uint32_t halfB = (uint32_t)(((lane >> 3) & 1) * 16);

    float acc[2][8][4];
    #pragma unroll
    for (int i = 0; i < 2; i++)
        #pragma unroll
        for (int j = 0; j < 8; j++)
            #pragma unroll
            for (int r = 0; r < 4; r++) acc[i][j][r] = 0.0f;

    stage_load(0, 0, vmax, sN, xhb, xlb, sb, tid);
    CP_COMMIT();

    for (int k = 0; k < K_; k++) {
        const int p = k & 1;
        if (k < K_ - 1) {
            stage_load(p ^ 1, k + 1, vmax, sN, xhb, xlb, sb, tid);
            CP_COMMIT();
            CP_WAIT1();
        } else {
            CP_WAIT0();
        }
        __syncthreads();

        const uint32_t aH = sb + SOFF_AHI(p);
        const uint32_t aL = sb + SOFF_ALO(p);
        const uint32_t wH = sb + SOFF_W(p);
        const uint32_t wL = wH + 8192;

        #pragma unroll
        for (int kk = 0; kk < 4; kk++) {
            uint32_t aHf[2][4], aLf[2][4];
            #pragma unroll
            for (int i = 0; i < 2; i++) {
                const uint32_t offA =
                    SWZ((uint32_t)((rowA + i * 16) * 128 + kk * 32) + halfA);
                LDM_X4(aHf[i][0], aHf[i][1], aHf[i][2], aHf[i][3], aH + offA);
                LDM_X4(aLf[i][0], aLf[i][1], aLf[i][2], aLf[i][3], aL + offA);
            }
            uint32_t bHf[8][2], bLf[8][2];
            #pragma unroll
            for (int jp = 0; jp < 4; jp++) {
                const uint32_t offB =
                    SWZ((uint32_t)((jp * 16 + rowB) * 128 + kk * 32) + halfB);
                LDM_X4(bHf[2 * jp][0], bHf[2 * jp][1],
                       bHf[2 * jp + 1][0], bHf[2 * jp + 1][1], wH + offB);
                LDM_X4(bLf[2 * jp][0], bLf[2 * jp][1],
                       bLf[2 * jp + 1][0], bLf[2 * jp + 1][1], wL + offB);
            }
            #pragma unroll
            for (int i = 0; i < 2; i++)
                #pragma unroll
                for (int j = 0; j < 8; j++) {
                    MMA16816(acc[i][j], aHf[i], bHf[j]);   // hi*hi
                    MMA16816(acc[i][j], aHf[i], bLf[j]);   // hi*lo
                    MMA16816(acc[i][j], aLf[i], bHf[j]);   // lo*hi
                }
        }
        __syncthreads();   // done reading buf p before it is overwritten
    }

    // ---- epilogue: regs -> smem stage [v*65 + o] -> coalesced stores ----
    {
        float* st = (float*)smem_raw;      // 256*65*4 = 66560 B, reuses buffers
        const int gid = lane >> 2;
        const int tg  = lane & 3;
        #pragma unroll
        for (int i = 0; i < 2; i++)
            #pragma unroll
            for (int j = 0; j < 8; j++)
                #pragma unroll
                for (int r = 0; r < 4; r++) {
                    const int v = mv + i * 16 + gid + (r >> 1) * 8;
                    const int o = j * 8 + 2 * tg + (r & 1);
                    st[v * 65 + o] = acc[i][j][r];
                }
        __syncthreads();

        const float* sBias = (const float*)(smem_raw + SOFF_BIAS);
        const int v = tid;
        if (v < vmax) {
            #pragma unroll
            for (int o = 0; o < C_; o++) {
                out[((size_t)b * C_ + o) * NV + n0 + v] = st[v * 65 + o] + sBias[o];
            }
        }
    }
}

// ---------------------------------------------------------------------------
// Launch
// ---------------------------------------------------------------------------
extern "C" void kernel_launch(void* const* d_in, const int* in_sizes, int n_in,
                              void* d_out, int out_size) {
    const float* x     = (const float*)d_in[0];
    const int*   neigh = (const int*)d_in[1];    // JAX x64 disabled -> int32
    const float* W     = (const float*)d_in[2];
    const float* bias  = (const float*)d_in[3];
    float*       out   = (float*)d_out;

    cudaFuncSetAttribute(iconv_mma_kernel,
                         cudaFuncAttributeMaxDynamicSharedMemorySize, SMEM_TOTAL);

    dim3 tgrid((NV + 31) / 32, C_ / 32, B_);
    xsplit_kernel<<<tgrid, dim3(32, 8)>>>(x);

    wprep_kernel<<<(K_ * C_ * C_ + 255) / 256, 256>>>(W);

    dim3 mgrid((NV + VT - 1) / VT, B_);          // (161, 8)
    iconv_mma_kernel<<<mgrid, 256, SMEM_TOTAL>>>(neigh, bias, out);
}

// round 7
// speedup vs baseline: 2.0522x; 1.0927x over previous
#include <cuda_runtime.h>
#include <cuda_bf16.h>
#include <stdint.h>

#define B_   8
#define C_   64
#define NV   40962
#define K_   7
#define CK   448
#define VT   128            // vertices per main CTA (2 CTAs/SM)

// ---------------------------------------------------------------------------
// Static device scratch (no runtime allocation allowed)
// ---------------------------------------------------------------------------
__device__ __align__(256) __nv_bfloat16 g_xhi[(size_t)B_ * NV * C_];  // [b][n][c] hi
__device__ __align__(256) __nv_bfloat16 g_xlo[(size_t)B_ * NV * C_];  // [b][n][c] lo
__device__ __align__(256) unsigned char g_wsw[K_ * 16384];            // [k][hi 8KB | lo 8KB], SW128

// ---------------------------------------------------------------------------
// PTX helpers (baseline-sm_100-legal: cp.async, ldmatrix, mma.sync)
// ---------------------------------------------------------------------------
__device__ __forceinline__ uint32_t smem_u32(const void* p) {
    uint32_t a;
    asm("{ .reg .u64 t; cvta.to.shared.u64 t, %1; cvt.u32.u64 %0, t; }" : "=r"(a) : "l"(p));
    return a;
}
#define CP16(dst, src) \
    asm volatile("cp.async.cg.shared.global [%0], [%1], 16;" :: "r"(dst), "l"(src) : "memory")
#define CP_COMMIT() asm volatile("cp.async.commit_group;" ::: "memory")
#define CP_WAIT1()  asm volatile("cp.async.wait_group 1;" ::: "memory")
#define CP_WAIT0()  asm volatile("cp.async.wait_group 0;" ::: "memory")

#define LDM_X4(r0, r1, r2, r3, a) \
    asm volatile("ldmatrix.sync.aligned.m8n8.x4.shared.b16 {%0,%1,%2,%3}, [%4];" \
                 : "=r"(r0), "=r"(r1), "=r"(r2), "=r"(r3) : "r"(a))

#define MMA16816(d, a, b) \
    asm volatile("mma.sync.aligned.m16n8k16.row.col.f32.bf16.bf16.f32 " \
                 "{%0,%1,%2,%3}, {%4,%5,%6,%7}, {%8,%9}, {%0,%1,%2,%3};" \
                 : "+f"((d)[0]), "+f"((d)[1]), "+f"((d)[2]), "+f"((d)[3]) \
                 : "r"((a)[0]), "r"((a)[1]), "r"((a)[2]), "r"((a)[3]), \
                   "r"((b)[0]), "r"((b)[1]))

#define SWZ(o) ((o) ^ (((o) >> 3) & 0x70))

// ---------------------------------------------------------------------------
// SMEM layout (bytes): stage = AHI 16K | ALO 16K | W 16K = 48K, x2 stages
// ---------------------------------------------------------------------------
#define SOFF_AHI(p)  ((p) * 49152)
#define SOFF_ALO(p)  ((p) * 49152 + 16384)
#define SOFF_W(p)    ((p) * 49152 + 32768)
#define SOFF_NEIGH   98304                   // VT*K_*4 = 3584
#define SOFF_BIAS    101888                  // 256
#define SMEM_TOTAL   102144                  // 2 CTAs/SM: 204.3KB

// ---------------------------------------------------------------------------
// Kernel 1: split-transpose x [B,C,N] -> xt_hi/xt_lo [B,N,C] bf16
// ---------------------------------------------------------------------------
__global__ void xsplit_kernel(const float* __restrict__ x) {
    __shared__ float tile[32][33];
    const int b  = blockIdx.z;
    const int c0 = blockIdx.y * 32;
    const int n0 = blockIdx.x * 32;
    const int tx = threadIdx.x, ty = threadIdx.y;

    #pragma unroll
    for (int s = 0; s < 4; s++) {
        const int c = c0 + ty + s * 8;
        const int n = n0 + tx;
        float v = 0.0f;
        if (n < NV) v = x[((size_t)b * C_ + c) * NV + n];
        tile[ty + s * 8][tx] = v;
    }
    __syncthreads();
    #pragma unroll
    for (int s = 0; s < 4; s++) {
        const int n = n0 + ty + s * 8;
        const int c = c0 + tx;
        if (n < NV) {
            const float v = tile[tx][ty + s * 8];
            const __nv_bfloat16 h = __float2bfloat16(v);
            const __nv_bfloat16 l = __float2bfloat16(v - __bfloat162float(h));
            const size_t o = ((size_t)b * NV + n) * C_ + c;
            g_xhi[o] = h;
            g_xlo[o] = l;
        }
    }
}

// ---------------------------------------------------------------------------
// Kernel 2: W [o][c*7+k] -> SW128-swizzled bf16 tiles [k][hi/lo][o rows 128B]
// ---------------------------------------------------------------------------
__global__ void wprep_kernel(const float* __restrict__ W) {
    const int e = blockIdx.x * 256 + threadIdx.x;   // over 7*64*64
    if (e >= K_ * C_ * C_) return;
    const int c = e & 63;
    const int o = (e >> 6) & 63;
    const int k = e >> 12;
    const float v = W[o * CK + c * K_ + k];
    const __nv_bfloat16 h = __float2bfloat16(v);
    const __nv_bfloat16 l = __float2bfloat16(v - __bfloat162float(h));
    const uint32_t sw = SWZ((uint32_t)(o * 128 + c * 2));
    *(__nv_bfloat16*)(g_wsw + (size_t)k * 16384 + sw)        = h;
    *(__nv_bfloat16*)(g_wsw + (size_t)k * 16384 + 8192 + sw) = l;
}

// ---------------------------------------------------------------------------
// Kernel 3: gather + mma.sync main kernel. 1 CTA = (batch, 128 vertices).
// 256 threads / 8 warps; warp = 32 vertices x 32 outputs; 2 CTAs per SM.
// ---------------------------------------------------------------------------
extern __shared__ char smem_raw[];

__device__ __forceinline__ void stage_load(
    int p, int k, int vmax, const int* sN,
    const __nv_bfloat16* xhb, const __nv_bfloat16* xlb,
    uint32_t sb, int tid)
{
    // 256 threads cover 128 rows x {hi,lo}: thread t -> row t>>1, part t&1
    const int v    = tid >> 1;
    const int part = tid & 1;
    const int j    = (v < vmax) ? sN[v * K_ + k] : 0;
    const char* src = (const char*)((part ? xlb : xhb) + (size_t)j * C_);
    const uint32_t abase = sb + (part ? SOFF_ALO(p) : SOFF_AHI(p));
    #pragma unroll
    for (int t = 0; t < 8; t++) {
        const uint32_t sw = SWZ((uint32_t)(v * 128 + t * 16));
        CP16(abase + sw, src + t * 16);
    }
    // W: 16KB pre-swizzled, 1024 CP16 over 256 threads
    const char* wsrc = (const char*)g_wsw + (size_t)k * 16384;
    const uint32_t wdst = sb + SOFF_W(p);
    #pragma unroll
    for (int i = 0; i < 4; i++) {
        const int idx = tid + i * 256;
        CP16(wdst + (uint32_t)idx * 16, wsrc + (size_t)idx * 16);
    }
}

__global__ __launch_bounds__(256, 2)
void iconv_mma_kernel(const int* __restrict__ neigh,
                      const float* __restrict__ bias,
                      float* __restrict__ out) {
    const uint32_t sb = smem_u32(smem_raw);
    const int tid  = threadIdx.x;
    const int lane = tid & 31;
    const int wid  = tid >> 5;
    const int b    = blockIdx.y;
    const int n0   = blockIdx.x * VT;
    const int vmax = min(VT, NV - n0);

    // stage bias + neighbor indices
    if (tid < C_) ((float*)(smem_raw + SOFF_BIAS))[tid] = bias[tid];
    {
        int* sN = (int*)(smem_raw + SOFF_NEIGH);
        const int lim = vmax * K_;
        #pragma unroll
        for (int i = 0; i < 4; i++) {
            const int q = tid + i * 256;
            if (q < VT * K_) sN[q] = (q < lim) ? neigh[(size_t)n0 * K_ + q] : 0;
        }
    }
    __syncthreads();

    const int* sN = (const int*)(smem_raw + SOFF_NEIGH);
    const __nv_bfloat16* xhb = g_xhi + (size_t)b * NV * C_;
    const __nv_bfloat16* xlb = g_xlo + (size_t)b * NV * C_;

    // warp tiling: 4 v-groups x 2 o-groups
    const int vg = wid >> 1;                  // 0..3 -> vertices [vg*32, +32)
    const int og = wid & 1;                   // 0..1 -> outputs  [og*32, +32)

    const int rowA = vg * 32 + (lane & 15);               // + i*16
    const uint32_t halfA = (uint32_t)((lane >> 4) * 16);
    const int rowB = (lane & 7) + ((lane >> 4) << 3);     // + og*32 + jp*16
    const uint32_t halfB = (uint32_t)(((lane >> 3) & 1) * 16);

    float acc[2][4][4];
    #pragma unroll
    for (int i = 0; i < 2; i++)
        #pragma unroll
        for (int j = 0; j < 4; j++)
            #pragma unroll
            for (int r = 0; r < 4; r++) acc[i][j][r] = 0.0f;

    stage_load(0, 0, vmax, sN, xhb, xlb, sb, tid);
    CP_COMMIT();

    for (int k = 0; k < K_; k++) {
        const int p = k & 1;
        if (k < K_ - 1) {
            stage_load(p ^ 1, k + 1, vmax, sN, xhb, xlb, sb, tid);
            CP_COMMIT();
            CP_WAIT1();
        } else {
            CP_WAIT0();
        }
        __syncthreads();

        const uint32_t aH = sb + SOFF_AHI(p);
        const uint32_t aL = sb + SOFF_ALO(p);
        const uint32_t wH = sb + SOFF_W(p);
        const uint32_t wL = wH + 8192;

        #pragma unroll
        for (int kk = 0; kk < 4; kk++) {
            uint32_t aHf[2][4], aLf[2][4];
            #pragma unroll
            for (int i = 0; i < 2; i++) {
                // half-offset must be added BEFORE the swizzle (no-carry there)
                const uint32_t offA =
                    SWZ((uint32_t)((rowA + i * 16) * 128 + kk * 32) + halfA);
                LDM_X4(aHf[i][0], aHf[i][1], aHf[i][2], aHf[i][3], aH + offA);
                LDM_X4(aLf[i][0], aLf[i][1], aLf[i][2], aLf[i][3], aL + offA);
            }
            uint32_t bHf[4][2], bLf[4][2];
            #pragma unroll
            for (int jp = 0; jp < 2; jp++) {
                const uint32_t offB =
                    SWZ((uint32_t)((og * 32 + jp * 16 + rowB) * 128 + kk * 32) + halfB);
                LDM_X4(bHf[2 * jp][0], bHf[2 * jp][1],
                       bHf[2 * jp + 1][0], bHf[2 * jp + 1][1], wH + offB);
                LDM_X4(bLf[2 * jp][0], bLf[2 * jp][1],
                       bLf[2 * jp + 1][0], bLf[2 * jp + 1][1], wL + offB);
            }
            #pragma unroll
            for (int i = 0; i < 2; i++)
                #pragma unroll
                for (int j = 0; j < 4; j++) {
                    MMA16816(acc[i][j], aHf[i], bHf[j]);   // hi*hi
                    MMA16816(acc[i][j], aHf[i], bLf[j]);   // hi*lo
                    MMA16816(acc[i][j], aLf[i], bHf[j]);   // lo*hi
                }
        }
        __syncthreads();   // done reading buf p before it is overwritten
    }

    // ---- epilogue: regs -> smem stage [v*65 + o] -> coalesced stores ----
    {
        float* st = (float*)smem_raw;      // 128*65*4 = 33,280 B (reuses stage 0)
        const int gid = lane >> 2;
        const int tg  = lane & 3;
        #pragma unroll
        for (int i = 0; i < 2; i++)
            #pragma unroll
            for (int j = 0; j < 4; j++)
                #pragma unroll
                for (int r = 0; r < 4; r++) {
                    const int v = vg * 32 + i * 16 + gid + (r >> 1) * 8;
                    const int o = og * 32 + j * 8 + 2 * tg + (r & 1);
                    st[v * 65 + o] = acc[i][j][r];
                }
        __syncthreads();

        const float* sBias = (const float*)(smem_raw + SOFF_BIAS);
        const int v  = tid & 127;          // 128 consecutive v -> full coalescing
        const int oh = (tid >> 7) * 32;    // output half
        if (v < vmax) {
            #pragma unroll
            for (int oo = 0; oo < 32; oo++) {
                const int o = oh + oo;
                out[((size_t)b * C_ + o) * NV + n0 + v] = st[v * 65 + o] + sBias[o];
            }
        }
    }
}

// ---------------------------------------------------------------------------
// Launch
// ---------------------------------------------------------------------------
extern "C" void kernel_launch(void* const* d_in, const int* in_sizes, int n_in,
                              void* d_out, int out_size) {
    const float* x     = (const float*)d_in[0];
    const int*   neigh = (const int*)d_in[1];    // JAX x64 disabled -> int32
    const float* W     = (const float*)d_in[2];
    const float* bias  = (const float*)d_in[3];
    float*       out   = (float*)d_out;

    cudaFuncSetAttribute(iconv_mma_kernel,
                         cudaFuncAttributeMaxDynamicSharedMemorySize, SMEM_TOTAL);

    dim3 tgrid((NV + 31) / 32, C_ / 32, B_);
    xsplit_kernel<<<tgrid, dim3(32, 8)>>>(x);

    wprep_kernel<<<(K_ * C_ * C_ + 255) / 256, 256>>>(W);

    dim3 mgrid((NV + VT - 1) / VT, B_);          // (321, 8)
    iconv_mma_kernel<<<mgrid, 256, SMEM_TOTAL>>>(neigh, bias, out);
}